// round 5
// baseline (speedup 1.0000x reference)
#include <cuda_runtime.h>
#include <math.h>

#define NN 8192
#define EMAX 262144
#define CB 64            // chain blocks (bid 0..CB-1); rest copy
#define GRID 444         // 148 SMs x 3 blocks -- guaranteed single wave
#define THREADS 256

// Scratch (allocation-free rule: device globals)
__device__ int   g_cnt   [NN];
__device__ int   g_fill  [NN];
__device__ int   g_rowptr[NN + 1];
__device__ int   g_col   [EMAX];
__device__ float g_dinv  [NN];
__device__ float g_h2    [NN * 8];
__device__ float g_x2    [NN * 8];
__device__ int   g_bar;        // chain stage barrier
__device__ int   g_copydone;   // copy blocks completed
__device__ int   g_exit;       // chain blocks done (reset protocol)

// Barrier among the CB chain blocks only (all wave-1 resident by construction).
__device__ __forceinline__ void chain_barrier(int target) {
    __threadfence();
    __syncthreads();
    if (threadIdx.x == 0) {
        atomicAdd(&g_bar, 1);
        while (atomicAdd(&g_bar, 0) < target) __nanosleep(100);
    }
    __syncthreads();
    __threadfence();
}

__global__ void __launch_bounds__(THREADS)
k_fused(const float4* __restrict__ src, float4* __restrict__ dst, long n4,
        const int* __restrict__ ei, int E,
        const float* __restrict__ W1, const float* __restrict__ b1,
        const float* __restrict__ W2, const float* __restrict__ b2,
        const float* __restrict__ Wfc, const float* __restrict__ bfc,
        const int* __restrict__ ue, int U)
{
    const int bid = blockIdx.x;
    const int CG  = GRID - CB;            // 380 copy blocks

    // ---------------- copy role: stream 256MB, never waits ----------------
    if (bid >= CB) {
        const long T = (long)CG * THREADS;
        long i = (long)(bid - CB) * THREADS + threadIdx.x;
        // 8-way unrolled moving front: ~12MB of loads in flight chip-wide
        for (; i + 7 * T < n4; i += 8 * T) {
            float4 a0 = src[i];
            float4 a1 = src[i + T];
            float4 a2 = src[i + 2 * T];
            float4 a3 = src[i + 3 * T];
            float4 a4 = src[i + 4 * T];
            float4 a5 = src[i + 5 * T];
            float4 a6 = src[i + 6 * T];
            float4 a7 = src[i + 7 * T];
            dst[i]         = a0;
            dst[i + T]     = a1;
            dst[i + 2 * T] = a2;
            dst[i + 3 * T] = a3;
            dst[i + 4 * T] = a4;
            dst[i + 5 * T] = a5;
            dst[i + 6 * T] = a6;
            dst[i + 7 * T] = a7;
        }
        for (; i < n4; i += T) dst[i] = src[i];
        __threadfence();                  // release copy writes
        __syncthreads();
        if (threadIdx.x == 0) atomicAdd(&g_copydone, 1);
        return;
    }

    // ---------------- chain role: CSR build + 2 GCN layers ----------------
    const int t0 = bid * THREADS + threadIdx.x;
    const int T  = CB * THREADS;          // 16384 chain threads
    const int lane  = threadIdx.x & 31;
    const int gbase = lane & 16;

    // stage 1: zero counters
    for (int i = t0; i < NN; i += T) { g_cnt[i] = 0; g_fill[i] = 0; }
    chain_barrier(CB * 1);

    // stage 2: in-degree histogram over dst
    for (int e = t0; e < E; e += T) atomicAdd(&g_cnt[ei[E + e]], 1);
    chain_barrier(CB * 2);

    // stage 3: scan -> rowptr, dinv (block 0 only)
    if (bid == 0) {
        __shared__ int sp[THREADS];
        int t = threadIdx.x;              // 256 threads, 32 elems each
        int base = t * 32;
        int s = 0;
#pragma unroll
        for (int k = 0; k < 32; k++) {
            int cv = g_cnt[base + k];
            g_rowptr[base + k] = s;       // local prefix; offset added below
            g_dinv[base + k] = rsqrtf((float)cv + 1.0f);
            s += cv;
        }
        sp[t] = s;
        __syncthreads();
        for (int o = 1; o < THREADS; o <<= 1) {
            int v = (t >= o) ? sp[t - o] : 0;
            __syncthreads();
            sp[t] += v;
            __syncthreads();
        }
        int off = sp[t] - s;
#pragma unroll
        for (int k = 0; k < 32; k++) g_rowptr[base + k] += off;
        if (t == THREADS - 1) g_rowptr[NN] = sp[THREADS - 1];
    }
    chain_barrier(CB * 3);

    // stage 4: CSR fill (bucket src by dst)
    for (int e = t0; e < E; e += T) {
        int s = ei[e];
        int d = ei[E + e];
        int p = g_rowptr[d] + atomicAdd(&g_fill[d], 1);
        g_col[p] = s;
    }
    chain_barrier(CB * 4);

    // stage 5: conv1 gather + bias + ReLU + 16x8 matmul (16 lanes/node)
    for (int t = t0; t < NN * 16; t += T) {
        int n = t >> 4;
        int f = t & 15;
        float dn  = g_dinv[n];
        int   beg = g_rowptr[n], end = g_rowptr[n + 1];
        float acc = 0.0f;
        for (int e = beg; e < end; e++) {
            int s = g_col[e];
            acc += g_dinv[s] * W1[(size_t)s * 16 + f];
        }
        float xf = fmaxf(dn * acc + dn * dn * W1[(size_t)n * 16 + f] + b1[f], 0.0f);
        float h = 0.0f;
#pragma unroll
        for (int k = 0; k < 16; k++) {
            float xk = __shfl_sync(0xffffffffu, xf, gbase + k);
            h += xk * W2[k * 8 + (f & 7)];
        }
        if (f < 8) g_h2[(size_t)n * 8 + f] = h;
    }
    chain_barrier(CB * 5);

    // stage 6: conv2 gather + bias + ReLU (8 lanes/node)
    for (int t = t0; t < NN * 8; t += T) {
        int n = t >> 3;
        int j = t & 7;
        float dn  = g_dinv[n];
        int   beg = g_rowptr[n], end = g_rowptr[n + 1];
        float acc = 0.0f;
        for (int e = beg; e < end; e++) {
            int s = g_col[e];
            acc += g_dinv[s] * g_h2[(size_t)s * 8 + j];
        }
        float v = dn * acc + dn * dn * g_h2[(size_t)n * 8 + j] + b2[j];
        g_x2[(size_t)n * 8 + j] = fmaxf(v, 0.0f);
    }
    chain_barrier(CB * 6);

    // wait for ALL copy writes (WAW ordering with edgeout overwrites).
    // All CG copy blocks are wave-1 resident, so this completes promptly.
    if (threadIdx.x == 0) {
        while (atomicAdd(&g_copydone, 0) < CG) __nanosleep(200);
    }
    __syncthreads();
    __threadfence();

    // stage 7: orientation head overwrites
    float wf[16];
#pragma unroll
    for (int f = 0; f < 16; f++) wf[f] = Wfc[f];
    float bias = bfc[0];
    float* outp = (float*)dst;
    for (int i = t0; i < U; i += T) {
        int u = ue[2 * i];
        int v = ue[2 * i + 1];
        float s = bias;
#pragma unroll
        for (int f = 0; f < 8; f++) {
            s += g_x2[(size_t)u * 8 + f] * wf[f];
            s += g_x2[(size_t)v * 8 + f] * wf[8 + f];
        }
        float o = 1.0f / (1.0f + expf(-s));
        outp[(size_t)u * NN + v] = o;
        outp[(size_t)v * NN + u] = 1.0f - o;
    }

    // exit protocol: block 0 resets counters after all chain blocks are done
    __threadfence();
    __syncthreads();
    if (threadIdx.x == 0) {
        atomicAdd(&g_exit, 1);
        if (bid == 0) {
            while (atomicAdd(&g_exit, 0) < CB) __nanosleep(100);
            g_bar = 0;
            g_copydone = 0;
            g_exit = 0;
            __threadfence();
        }
    }
}

extern "C" void kernel_launch(void* const* d_in, const int* in_sizes, int n_in,
                              void* d_out, int out_size) {
    const float* adj = (const float*)d_in[0];
    const float* W1  = (const float*)d_in[1];
    const float* b1  = (const float*)d_in[2];
    const float* W2  = (const float*)d_in[3];
    const float* b2  = (const float*)d_in[4];
    const float* Wfc = (const float*)d_in[5];
    const float* bfc = (const float*)d_in[6];
    const int*   ei  = (const int*)d_in[7];
    const int*   ue  = (const int*)d_in[8];

    int E = in_sizes[7] / 2;
    int U = in_sizes[8] / 2;
    long n4 = (long)out_size / 4;      // NN*NN divisible by 4

    k_fused<<<GRID, THREADS>>>((const float4*)adj, (float4*)d_out, n4,
                               ei, E, W1, b1, W2, b2, Wfc, bfc, ue, U);
}

// round 6
// speedup vs baseline: 1.3029x; 1.3029x over previous
#include <cuda_runtime.h>
#include <math.h>

#define NN 8192
#define EMAX 262144

// Scratch (allocation-free rule: device globals)
__device__ int   g_cnt   [NN];
__device__ int   g_fill  [NN];
__device__ int   g_rowptr[NN + 1];
__device__ int   g_col   [EMAX];
__device__ float g_dinv  [NN];
__device__ float g_h2    [NN * 8];
__device__ float g_x2    [NN * 8];

// ---------------------------------------------------------------------------
// 1. zero the two int counters
__global__ void k_zero() {
    int i = blockIdx.x * blockDim.x + threadIdx.x;
    if (i < NN) { g_cnt[i] = 0; g_fill[i] = 0; }
}

// 2. in-degree histogram over dst
__global__ void k_count(const int* __restrict__ ei, int E) {
    int e = blockIdx.x * blockDim.x + threadIdx.x;
    if (e < E) atomicAdd(&g_cnt[ei[E + e]], 1);
}

// 3. single-block exclusive scan of cnt -> rowptr, plus dinv = rsqrt(deg+1)
__global__ void k_scan() {
    __shared__ int sp[256];
    int t = threadIdx.x;                 // 256 threads, 32 elems each
    int base = t * 32;
    int s = 0;
    int pre[32];
#pragma unroll
    for (int k = 0; k < 32; k++) {
        int cv = g_cnt[base + k];
        pre[k] = s;
        g_dinv[base + k] = rsqrtf((float)cv + 1.0f);
        s += cv;
    }
    sp[t] = s;
    __syncthreads();
    for (int o = 1; o < 256; o <<= 1) {  // inclusive Hillis-Steele
        int v = (t >= o) ? sp[t - o] : 0;
        __syncthreads();
        sp[t] += v;
        __syncthreads();
    }
    int off = sp[t] - s;                 // exclusive offset
#pragma unroll
    for (int k = 0; k < 32; k++) g_rowptr[base + k] = off + pre[k];
    if (t == 255) g_rowptr[NN] = sp[255];
}

// 4. CSR fill: bucket src by dst
__global__ void k_fill(const int* __restrict__ ei, int E) {
    int e = blockIdx.x * blockDim.x + threadIdx.x;
    if (e >= E) return;
    int s = ei[e];
    int d = ei[E + e];
    int p = g_rowptr[d] + atomicAdd(&g_fill[d], 1);
    g_col[p] = s;
}

// 5. conv1 gather + bias + ReLU + 16x8 matmul (16 lanes per node, shfl)
__global__ void k_conv1(const float* __restrict__ W1,
                        const float* __restrict__ b1,
                        const float* __restrict__ W2) {
    int tid  = blockIdx.x * blockDim.x + threadIdx.x;
    int n    = tid >> 4;                 // 16 lanes per node
    int f    = tid & 15;
    if (n >= NN) return;
    int lane  = threadIdx.x & 31;
    int gbase = lane & 16;

    float dn  = g_dinv[n];
    int   beg = g_rowptr[n], end = g_rowptr[n + 1];
    float acc = 0.0f;
    for (int e = beg; e < end; e++) {
        int s = g_col[e];
        acc += g_dinv[s] * W1[(size_t)s * 16 + f];
    }
    float xf = fmaxf(dn * acc + dn * dn * W1[(size_t)n * 16 + f] + b1[f], 0.0f);

    float h = 0.0f;
#pragma unroll
    for (int k = 0; k < 16; k++) {
        float xk = __shfl_sync(0xffffffffu, xf, gbase + k);
        h += xk * W2[k * 8 + (f & 7)];
    }
    if (f < 8) g_h2[(size_t)n * 8 + f] = h;
}

// 6. conv2 gather + bias + ReLU (8 lanes per node)
__global__ void k_conv2(const float* __restrict__ b2) {
    int tid = blockIdx.x * blockDim.x + threadIdx.x;
    int n   = tid >> 3;                  // 8 lanes per node
    int j   = tid & 7;
    if (n >= NN) return;

    float dn  = g_dinv[n];
    int   beg = g_rowptr[n], end = g_rowptr[n + 1];
    float acc = 0.0f;
    for (int e = beg; e < end; e++) {
        int s = g_col[e];
        acc += g_dinv[s] * g_h2[(size_t)s * 8 + j];
    }
    float v = dn * acc + dn * dn * g_h2[(size_t)n * 8 + j] + b2[j];
    g_x2[(size_t)n * 8 + j] = fmaxf(v, 0.0f);
}

// 7. bulk copy adjacency -> out (float4; empirically ~5.5 TB/s = LTS cap)
__global__ void k_copy(const float4* __restrict__ src, float4* __restrict__ dst,
                       int n4) {
    int i = blockIdx.x * blockDim.x + threadIdx.x;
    if (i < n4) dst[i] = src[i];
}

// 8. orientation head: out[u,v] = sigmoid(ef @ Wfc + bfc); out[v,u] = 1 - it
__global__ void k_edgeout(const int* __restrict__ ue,
                          const float* __restrict__ Wfc,
                          const float* __restrict__ bfc,
                          float* __restrict__ out, int U) {
    int i = blockIdx.x * blockDim.x + threadIdx.x;
    if (i >= U) return;
    int u = ue[2 * i];
    int v = ue[2 * i + 1];
    float s = bfc[0];
#pragma unroll
    for (int f = 0; f < 8; f++) {
        s += g_x2[(size_t)u * 8 + f] * Wfc[f];
        s += g_x2[(size_t)v * 8 + f] * Wfc[8 + f];
    }
    float o = 1.0f / (1.0f + expf(-s));
    out[(size_t)u * NN + v] = o;
    out[(size_t)v * NN + u] = 1.0f - o;
}

extern "C" void kernel_launch(void* const* d_in, const int* in_sizes, int n_in,
                              void* d_out, int out_size) {
    const float* adj = (const float*)d_in[0];
    const float* W1  = (const float*)d_in[1];
    const float* b1  = (const float*)d_in[2];
    const float* W2  = (const float*)d_in[3];
    const float* b2  = (const float*)d_in[4];
    const float* Wfc = (const float*)d_in[5];
    const float* bfc = (const float*)d_in[6];
    const int*   ei  = (const int*)d_in[7];
    const int*   ue  = (const int*)d_in[8];

    int E = in_sizes[7] / 2;
    int U = in_sizes[8] / 2;

    const int B = 256;

    // Fork-join: chain runs on a high-priority side stream concurrent with the
    // big copy on the launch stream. Streams/events are created fresh per call
    // (kernel_launch runs only a couple of times; host handles only, no device
    // memory) and intentionally not destroyed so graph capture stays valid.
    int loPri = 0, hiPri = 0;
    cudaDeviceGetStreamPriorityRange(&loPri, &hiPri);
    cudaStream_t s2;
    cudaStreamCreateWithPriority(&s2, cudaStreamNonBlocking, hiPri);
    cudaEvent_t evFork, evChain;
    cudaEventCreateWithFlags(&evFork,  cudaEventDisableTiming);
    cudaEventCreateWithFlags(&evChain, cudaEventDisableTiming);

    // fork
    cudaEventRecord(evFork, 0);
    cudaStreamWaitEvent(s2, evFork, 0);

    // ---- side stream: CSR build + 2 GCN layers (~32us, DRAM-light) ----
    k_zero <<<(NN + B - 1) / B, B, 0, s2>>>();
    k_count<<<(E + B - 1) / B, B, 0, s2>>>(ei, E);
    k_scan <<<1, 256, 0, s2>>>();
    k_fill <<<(E + B - 1) / B, B, 0, s2>>>(ei, E);
    k_conv1<<<(NN * 16 + B - 1) / B, B, 0, s2>>>(W1, b1, W2);
    k_conv2<<<(NN * 8 + B - 1) / B, B, 0, s2>>>(b2);
    cudaEventRecord(evChain, s2);

    // ---- main stream: HBM-bound adjacency copy (~93us) ----
    int n4 = out_size / 4;               // NN*NN divisible by 4
    k_copy<<<(n4 + B - 1) / B, B>>>((const float4*)adj, (float4*)d_out, n4);

    // join: edgeout needs both the copy (WAW on d_out) and the chain (x2)
    cudaStreamWaitEvent(0, evChain, 0);
    k_edgeout<<<(U + B - 1) / B, B>>>(ue, Wfc, bfc, (float*)d_out, U);
}